// round 10
// baseline (speedup 1.0000x reference)
#include <cuda_runtime.h>
#include <math_constants.h>

// Sampler: B=256 rows, V=128000 vocab.
// inputs: logits [B,V] f32, temperatures [B] f32, uniform_noise [B,V] f32
// output: [tokens (B floats)] ++ [probs (B*V floats)]

#define NT 1024
#define BB 256
#define VV 128000
#define NV8 (VV / 8)                  // 16000 float8 chunks per row
#define L2E 1.4426950408889634f
#define LN2 0.6931471805599453f
#define JPIN ((NV8 * 3) / 4)          // pin first 3/4 of each row in L2

__device__ __forceinline__ float lg2a(float x) {
    float r; asm("lg2.approx.f32 %0, %1;" : "=f"(r) : "f"(x)); return r;
}
__device__ __forceinline__ float ex2a(float x) {
    float r; asm("ex2.approx.f32 %0, %1;" : "=f"(r) : "f"(x)); return r;
}
__device__ __forceinline__ void unpack8(unsigned long long a0, unsigned long long a1,
                                        unsigned long long a2, unsigned long long a3,
                                        float v[8]) {
    v[0] = __uint_as_float((unsigned)(a0));  v[1] = __uint_as_float((unsigned)(a0 >> 32));
    v[2] = __uint_as_float((unsigned)(a1));  v[3] = __uint_as_float((unsigned)(a1 >> 32));
    v[4] = __uint_as_float((unsigned)(a2));  v[5] = __uint_as_float((unsigned)(a2 >> 32));
    v[6] = __uint_as_float((unsigned)(a3));  v[7] = __uint_as_float((unsigned)(a3 >> 32));
}
// 32-byte logits load, pinned toward L2 retention (pass-2 reread)
__device__ __forceinline__ void ldg_el8(const float* p, float v[8]) {
    unsigned long long a0, a1, a2, a3;
    asm("ld.global.L2::evict_last.v4.b64 {%0,%1,%2,%3}, [%4];"
        : "=l"(a0), "=l"(a1), "=l"(a2), "=l"(a3) : "l"(p));
    unpack8(a0, a1, a2, a3, v);
}
// 32-byte plain load
__device__ __forceinline__ void ldg8(const float* p, float v[8]) {
    unsigned long long a0, a1, a2, a3;
    asm("ld.global.v4.b64 {%0,%1,%2,%3}, [%4];"
        : "=l"(a0), "=l"(a1), "=l"(a2), "=l"(a3) : "l"(p));
    unpack8(a0, a1, a2, a3, v);
}

__global__ void __launch_bounds__(NT, 2)   // cap regs at 32 -> 2 blocks/SM
sampler_kernel(const float* __restrict__ logits,
               const float* __restrict__ temps,
               const float* __restrict__ noise,
               float* __restrict__ out)
{
    const int b    = blockIdx.x;
    const int tid  = threadIdx.x;
    const int lane = tid & 31;
    const int wid  = tid >> 5;            // 0..31

    const float t      = temps[b];
    const float safe_t = (t == 0.0f) ? 1.0f : t;
    const float inv_t  = 1.0f / safe_t;
    const float a      = inv_t * L2E;     // logit -> log2-domain scale

    const float* __restrict__ lrow = logits + (size_t)b * VV;
    const float* __restrict__ nrow = noise  + (size_t)b * VV;
    float4* __restrict__ prow      = (float4*)(out + BB + (size_t)b * VV);

    // pass 1: greedy argmax + Gumbel argmax + online exp-sum (base = running gv)
    float gv = -CUDART_INF_F; int gi = 0;
    float sv = -CUDART_INF_F; int si = 0;
    float s  = 0.0f;          // sum of exp2(l*a + neg_gva)
    float neg_gva = 0.0f;     // = -gv*a once gv is finite (first branch always taken)

    for (int j = tid; j < NV8; j += NT) {
        float lv[8];
        if (j < JPIN) ldg_el8(lrow + 8 * j, lv);
        else          ldg8(lrow + 8 * j, lv);
        // consume in two 4-wide halves to keep live ranges small
        #pragma unroll
        for (int h = 0; h < 2; h++) {
            const float4 n4 = __ldcs((const float4*)(nrow + 8 * j) + h);
            const float nv[4] = {n4.x, n4.y, n4.z, n4.w};
            #pragma unroll
            for (int k = 0; k < 4; k++) {
                const int idx = 8 * j + 4 * h + k;
                const float l = lv[4 * h + k];
                const float u = nv[k];
                // greedy argmax + online exp-sum share the branch
                if (l > gv) {
                    s = s * ex2a((gv - l) * a) + 1.0f;  // rebase (exp2(-inf)=0 first time)
                    gv = l; gi = idx;
                    neg_gva = -gv * a;
                } else {
                    s += ex2a(fmaf(l, a, neg_gva));
                }
                // Gumbel: y = -log(u); fast LG2 + exact series fixup for u -> 1 tail
                float y = (-LN2) * lg2a(u);
                const float d = 1.0f - u;
                if (u > 0.99f)
                    y = d * fmaf(d, fmaf(d, 0.33333333f, 0.5f), 1.0f);
                const float z = fmaf(lg2a(y), -LN2, l * inv_t);   // l/t + g
                if (z > sv) { sv = z; si = idx; }
            }
        }
    }

    // ---- block reductions ----
    __shared__ float sh_gv[32]; __shared__ int sh_gi[32];
    __shared__ float sh_sv[32]; __shared__ int sh_si[32];
    __shared__ float sh_sum[32];
    __shared__ float fin_c;

    #pragma unroll
    for (int off = 16; off; off >>= 1) {
        float v  = __shfl_xor_sync(0xffffffffu, gv, off);
        int   i  = __shfl_xor_sync(0xffffffffu, gi, off);
        float ws = __shfl_xor_sync(0xffffffffu, s, off);
        if (v > gv) { s = fmaf(s, ex2a((gv - v) * a), ws); gv = v; gi = i; }
        else {
            s = fmaf(ws, ex2a((v - gv) * a), s);
            if (v == gv && i < gi) gi = i;
        }
        float v2 = __shfl_xor_sync(0xffffffffu, sv, off);
        int   i2 = __shfl_xor_sync(0xffffffffu, si, off);
        if (v2 > sv || (v2 == sv && i2 < si)) { sv = v2; si = i2; }
    }
    if (lane == 0) {
        sh_gv[wid] = gv; sh_gi[wid] = gi; sh_sum[wid] = s;
        sh_sv[wid] = sv; sh_si[wid] = si;
    }
    __syncthreads();

    if (wid == 0) {
        float v = sh_gv[lane]; int i = sh_gi[lane]; float c = sh_sum[lane];
        float v2 = sh_sv[lane]; int i2 = sh_si[lane];
        #pragma unroll
        for (int off = 16; off; off >>= 1) {
            float wv = __shfl_xor_sync(0xffffffffu, v, off);
            int   wi = __shfl_xor_sync(0xffffffffu, i, off);
            float wc = __shfl_xor_sync(0xffffffffu, c, off);
            if (wv > v) { c = fmaf(c, ex2a((v - wv) * a), wc); v = wv; i = wi; }
            else {
                c = fmaf(wc, ex2a((wv - v) * a), c);
                if (wv == v && wi < i) i = wi;
            }
            float wv2 = __shfl_xor_sync(0xffffffffu, v2, off);
            int   wi2 = __shfl_xor_sync(0xffffffffu, i2, off);
            if (wv2 > v2 || (wv2 == v2 && wi2 < i2)) { v2 = wv2; i2 = wi2; }
        }
        if (lane == 0) {
            // probs = exp2(l*a - max*a - log2(sum))
            fin_c = fmaf(-v, a, -log2f(c));
            out[b] = (float)((t == 0.0f) ? i : i2);
        }
    }
    __syncthreads();

    // ---- pass 2: probs = exp2(l*a + c) ----
    // REVERSE order (LIFO): unpinned row tail is freshest in L2; pinned head
    // survives via evict_last. 256-bit loads, x2 unroll for MLP.
    const float c = fin_c;
    int j = tid + ((NV8 - 1 - tid) / NT) * NT;    // this thread's top chunk
    for (; j >= NT; j -= 2 * NT) {
        float la[8], lb[8];
        ldg8(lrow + 8 * j, la);
        ldg8(lrow + 8 * (j - NT), lb);
        float4 p0, p1, q0, q1;
        p0.x = ex2a(fmaf(la[0], a, c)); p0.y = ex2a(fmaf(la[1], a, c));
        p0.z = ex2a(fmaf(la[2], a, c)); p0.w = ex2a(fmaf(la[3], a, c));
        p1.x = ex2a(fmaf(la[4], a, c)); p1.y = ex2a(fmaf(la[5], a, c));
        p1.z = ex2a(fmaf(la[6], a, c)); p1.w = ex2a(fmaf(la[7], a, c));
        q0.x = ex2a(fmaf(lb[0], a, c)); q0.y = ex2a(fmaf(lb[1], a, c));
        q0.z = ex2a(fmaf(lb[2], a, c)); q0.w = ex2a(fmaf(lb[3], a, c));
        q1.x = ex2a(fmaf(lb[4], a, c)); q1.y = ex2a(fmaf(lb[5], a, c));
        q1.z = ex2a(fmaf(lb[6], a, c)); q1.w = ex2a(fmaf(lb[7], a, c));
        __stcs(prow + 2 * j, p0);       __stcs(prow + 2 * j + 1, p1);
        __stcs(prow + 2 * (j - NT), q0); __stcs(prow + 2 * (j - NT) + 1, q1);
    }
    if (j >= 0) {
        float la[8];
        ldg8(lrow + 8 * j, la);
        float4 p0, p1;
        p0.x = ex2a(fmaf(la[0], a, c)); p0.y = ex2a(fmaf(la[1], a, c));
        p0.z = ex2a(fmaf(la[2], a, c)); p0.w = ex2a(fmaf(la[3], a, c));
        p1.x = ex2a(fmaf(la[4], a, c)); p1.y = ex2a(fmaf(la[5], a, c));
        p1.z = ex2a(fmaf(la[6], a, c)); p1.w = ex2a(fmaf(la[7], a, c));
        __stcs(prow + 2 * j, p0);       __stcs(prow + 2 * j + 1, p1);
    }
}

extern "C" void kernel_launch(void* const* d_in, const int* in_sizes, int n_in,
                              void* d_out, int out_size) {
    const float* logits = (const float*)d_in[0];
    const float* temps  = (const float*)d_in[1];
    const float* noise  = (const float*)d_in[2];
    float* out = (float*)d_out;
    sampler_kernel<<<BB, NT>>>(logits, temps, noise, out);
}

// round 11
// speedup vs baseline: 1.1008x; 1.1008x over previous
#include <cuda_runtime.h>
#include <math_constants.h>

// Sampler: B=256 rows, V=128000 vocab.
// inputs: logits [B,V] f32, temperatures [B] f32, uniform_noise [B,V] f32
// output: [tokens (B floats)] ++ [probs (B*V floats)]

#define NT 1024
#define BB 256
#define VV 128000
#define NV8 (VV / 8)                  // 16000 float8 chunks per row (pass 1)
#define NV4 (VV / 4)                  // 32000 float4 chunks per row (pass 2)
#define L2E 1.4426950408889634f

__device__ __forceinline__ float lg2a(float x) {
    float r; asm("lg2.approx.f32 %0, %1;" : "=f"(r) : "f"(x)); return r;
}
__device__ __forceinline__ float ex2a(float x) {
    float r; asm("ex2.approx.f32 %0, %1;" : "=f"(r) : "f"(x)); return r;
}
// 32-byte logits load, pinned toward L2 retention for the pass-2 reread.
// (sm_103a ptxas requires .v8.b32/.v4.b64 with L2::evict_last)
__device__ __forceinline__ void ldg_el8(const float* p, float v[8]) {
    unsigned long long a0, a1, a2, a3;
    asm("ld.global.L2::evict_last.v4.b64 {%0,%1,%2,%3}, [%4];"
        : "=l"(a0), "=l"(a1), "=l"(a2), "=l"(a3) : "l"(p));
    v[0] = __uint_as_float((unsigned)(a0));  v[1] = __uint_as_float((unsigned)(a0 >> 32));
    v[2] = __uint_as_float((unsigned)(a1));  v[3] = __uint_as_float((unsigned)(a1 >> 32));
    v[4] = __uint_as_float((unsigned)(a2));  v[5] = __uint_as_float((unsigned)(a2 >> 32));
    v[6] = __uint_as_float((unsigned)(a3));  v[7] = __uint_as_float((unsigned)(a3 >> 32));
}

__global__ void __launch_bounds__(NT, 2)   // cap regs at 32 -> 2 blocks/SM
sampler_kernel(const float* __restrict__ logits,
               const float* __restrict__ temps,
               const float* __restrict__ noise,
               float* __restrict__ out)
{
    const int b    = blockIdx.x;
    const int tid  = threadIdx.x;
    const int lane = tid & 31;
    const int wid  = tid >> 5;            // 0..31

    const float t      = temps[b];
    const float safe_t = (t == 0.0f) ? 1.0f : t;
    const float inv_t  = 1.0f / safe_t;
    const float a      = inv_t * L2E;     // logit -> log2-domain scale

    const float* __restrict__ lrow = logits + (size_t)b * VV;
    const float* __restrict__ nrow = noise  + (size_t)b * VV;
    float4* __restrict__ prow      = (float4*)(out + BB + (size_t)b * VV);

    // pass 1 (all in log2 domain):
    //   greedy argmax on raw l (must be exact for t==0 rows)
    //   exp-sum s = sum exp2(la + neg_gva), la = l*a, neg_gva = -gvmax*a
    //   Gumbel key z = la - lg2(-lg2(u))  (const lg2(ln2) offset dropped)
    float gv = -CUDART_INF_F; int gi = 0;
    float sv = -CUDART_INF_F; int si = 0;
    float s  = 0.0f;
    float neg_gva = 0.0f;     // set on first rebase (always taken)

    for (int j = tid; j < NV8; j += NT) {
        float lv[8];
        ldg_el8(lrow + 8 * j, lv);
        // consume in two 4-wide halves to keep live ranges small
        #pragma unroll
        for (int h = 0; h < 2; h++) {
            const float4 n4 = __ldcs((const float4*)(nrow + 8 * j) + h);
            const float nv[4] = {n4.x, n4.y, n4.z, n4.w};
            #pragma unroll
            for (int k = 0; k < 4; k++) {
                const int idx = 8 * j + 4 * h + k;
                const float l  = lv[4 * h + k];
                const float u  = nv[k];
                const float la = l * a;
                // greedy argmax + online exp-sum share the branch
                if (l > gv) {
                    s = s * ex2a(fmaf(gv, a, -la)) + 1.0f;  // exp2((gv-l)*a); -inf first time
                    gv = l; gi = idx;
                    neg_gva = -la;
                } else {
                    s += ex2a(la + neg_gva);
                }
                // y2 = -log2(u); exact-series fixup (pre-scaled by L2E) for u -> 1
                float y2 = 0.0f - lg2a(u);
                const float d = 1.0f - u;
                if (u > 0.99f)
                    y2 = d * fmaf(d, fmaf(d, 0.48089835f, 0.72134752f), 1.44269504f);
                const float z = la - lg2a(y2);           // log2-domain Gumbel key
                if (z > sv) { sv = z; si = idx; }
            }
        }
    }

    // ---- block reductions ----
    __shared__ float sh_gv[32]; __shared__ int sh_gi[32];
    __shared__ float sh_sv[32]; __shared__ int sh_si[32];
    __shared__ float sh_sum[32];
    __shared__ float fin_c;

    #pragma unroll
    for (int off = 16; off; off >>= 1) {
        float v  = __shfl_xor_sync(0xffffffffu, gv, off);
        int   i  = __shfl_xor_sync(0xffffffffu, gi, off);
        float ws = __shfl_xor_sync(0xffffffffu, s, off);
        if (v > gv) { s = fmaf(s, ex2a((gv - v) * a), ws); gv = v; gi = i; }
        else {
            s = fmaf(ws, ex2a((v - gv) * a), s);
            if (v == gv && i < gi) gi = i;
        }
        float v2 = __shfl_xor_sync(0xffffffffu, sv, off);
        int   i2 = __shfl_xor_sync(0xffffffffu, si, off);
        if (v2 > sv || (v2 == sv && i2 < si)) { sv = v2; si = i2; }
    }
    if (lane == 0) {
        sh_gv[wid] = gv; sh_gi[wid] = gi; sh_sum[wid] = s;
        sh_sv[wid] = sv; sh_si[wid] = si;
    }
    __syncthreads();

    if (wid == 0) {
        float v = sh_gv[lane]; int i = sh_gi[lane]; float c = sh_sum[lane];
        float v2 = sh_sv[lane]; int i2 = sh_si[lane];
        #pragma unroll
        for (int off = 16; off; off >>= 1) {
            float wv = __shfl_xor_sync(0xffffffffu, v, off);
            int   wi = __shfl_xor_sync(0xffffffffu, i, off);
            float wc = __shfl_xor_sync(0xffffffffu, c, off);
            if (wv > v) { c = fmaf(c, ex2a((v - wv) * a), wc); v = wv; i = wi; }
            else {
                c = fmaf(wc, ex2a((wv - v) * a), c);
                if (wv == v && wi < i) i = wi;
            }
            float wv2 = __shfl_xor_sync(0xffffffffu, v2, off);
            int   wi2 = __shfl_xor_sync(0xffffffffu, i2, off);
            if (wv2 > v2 || (wv2 == v2 && wi2 < i2)) { v2 = wv2; i2 = wi2; }
        }
        if (lane == 0) {
            // probs = exp2(l*a - max*a - log2(sum))
            fin_c = fmaf(-v, a, -log2f(c));
            out[b] = (float)((t == 0.0f) ? i : i2);
        }
    }
    __syncthreads();

    // ---- pass 2: probs = exp2(l*a + c) ----
    // REVERSE order (LIFO): the row tail is the freshest L2 content after
    // pass 1; consuming most-recent-first maximizes hits under LRU.
    // Unrolled x2 for per-thread MLP in the load->EX2->store chain.
    const float c = fin_c;
    const float4* __restrict__ lrow4 = (const float4*)lrow;
    int j = NV4 - NT + tid;               // top chunk for this thread
    for (; j >= NT; j -= 2 * NT) {
        const float4 la4 = lrow4[j];
        const float4 lb4 = lrow4[j - NT];
        float4 pa, pb;
        pa.x = ex2a(fmaf(la4.x, a, c)); pa.y = ex2a(fmaf(la4.y, a, c));
        pa.z = ex2a(fmaf(la4.z, a, c)); pa.w = ex2a(fmaf(la4.w, a, c));
        pb.x = ex2a(fmaf(lb4.x, a, c)); pb.y = ex2a(fmaf(lb4.y, a, c));
        pb.z = ex2a(fmaf(lb4.z, a, c)); pb.w = ex2a(fmaf(lb4.w, a, c));
        __stcs(prow + j, pa);
        __stcs(prow + (j - NT), pb);
    }
    if (j >= 0) {
        const float4 la4 = lrow4[j];
        float4 pa;
        pa.x = ex2a(fmaf(la4.x, a, c)); pa.y = ex2a(fmaf(la4.y, a, c));
        pa.z = ex2a(fmaf(la4.z, a, c)); pa.w = ex2a(fmaf(la4.w, a, c));
        __stcs(prow + j, pa);
    }
}

extern "C" void kernel_launch(void* const* d_in, const int* in_sizes, int n_in,
                              void* d_out, int out_size) {
    const float* logits = (const float*)d_in[0];
    const float* temps  = (const float*)d_in[1];
    const float* noise  = (const float*)d_in[2];
    float* out = (float*)d_out;
    sampler_kernel<<<BB, NT>>>(logits, temps, noise, out);
}

// round 12
// speedup vs baseline: 1.1150x; 1.0129x over previous
#include <cuda_runtime.h>
#include <math_constants.h>

// Sampler: B=256 rows, V=128000 vocab.
// inputs: logits [B,V] f32, temperatures [B] f32, uniform_noise [B,V] f32
// output: [tokens (B floats)] ++ [probs (B*V floats)]

#define NT 1024
#define BB 256
#define VV 128000
#define NV8 (VV / 8)                  // 16000 float8 chunks per row (pass 1)
#define NV4 (VV / 4)                  // 32000 float4 chunks per row (pass 2)
#define JPIN ((NV8 * 3) / 4)          // 12000: first 3/4 of row gets evict_last (96MB set)
#define L2E 1.4426950408889634f
#define LN2 0.6931471805599453f

__device__ __forceinline__ float lg2a(float x) {
    float r; asm("lg2.approx.f32 %0, %1;" : "=f"(r) : "f"(x)); return r;
}
__device__ __forceinline__ float ex2a(float x) {
    float r; asm("ex2.approx.f32 %0, %1;" : "=f"(r) : "f"(x)); return r;
}
__device__ __forceinline__ void unpack8(unsigned long long a0, unsigned long long a1,
                                        unsigned long long a2, unsigned long long a3,
                                        float v[8]) {
    v[0] = __uint_as_float((unsigned)(a0));  v[1] = __uint_as_float((unsigned)(a0 >> 32));
    v[2] = __uint_as_float((unsigned)(a1));  v[3] = __uint_as_float((unsigned)(a1 >> 32));
    v[4] = __uint_as_float((unsigned)(a2));  v[5] = __uint_as_float((unsigned)(a2 >> 32));
    v[6] = __uint_as_float((unsigned)(a3));  v[7] = __uint_as_float((unsigned)(a3 >> 32));
}
// 32-byte logits load, pinned toward L2 retention for the pass-2 reread.
// (sm_103a ptxas requires .v8.b32/.v4.b64 with L2::evict_last)
__device__ __forceinline__ void ldg_el8(const float* p, float v[8]) {
    unsigned long long a0, a1, a2, a3;
    asm("ld.global.L2::evict_last.v4.b64 {%0,%1,%2,%3}, [%4];"
        : "=l"(a0), "=l"(a1), "=l"(a2), "=l"(a3) : "l"(p));
    unpack8(a0, a1, a2, a3, v);
}
// 32-byte plain load (unpinned tail)
__device__ __forceinline__ void ldg8(const float* p, float v[8]) {
    unsigned long long a0, a1, a2, a3;
    asm("ld.global.v4.b64 {%0,%1,%2,%3}, [%4];"
        : "=l"(a0), "=l"(a1), "=l"(a2), "=l"(a3) : "l"(p));
    unpack8(a0, a1, a2, a3, v);
}

// shared pass-1 element body (identical arithmetic to the proven R8 kernel)
#define P1_BODY(LV, JJ)                                                        \
    _Pragma("unroll")                                                          \
    for (int h = 0; h < 2; h++) {                                              \
        const float4 n4 = __ldcs((const float4*)(nrow + 8 * (JJ)) + h);        \
        const float nv[4] = {n4.x, n4.y, n4.z, n4.w};                          \
        _Pragma("unroll")                                                      \
        for (int k = 0; k < 4; k++) {                                          \
            const int idx = 8 * (JJ) + 4 * h + k;                              \
            const float l = LV[4 * h + k];                                     \
            const float u = nv[k];                                             \
            if (l > gv) {                                                      \
                s = s * ex2a((gv - l) * a) + 1.0f;                             \
                gv = l; gi = idx;                                              \
            } else {                                                           \
                s += ex2a((l - gv) * a);                                       \
            }                                                                  \
            float y = (-LN2) * lg2a(u);                                        \
            const float d = 1.0f - u;                                          \
            if (u > 0.99f)                                                     \
                y = d * fmaf(d, fmaf(d, 0.33333333f, 0.5f), 1.0f);             \
            const float z = fmaf(lg2a(y), -LN2, l * inv_t);                    \
            if (z > sv) { sv = z; si = idx; }                                  \
        }                                                                      \
    }

__global__ void __launch_bounds__(NT, 2)   // cap regs at 32 -> 2 blocks/SM
sampler_kernel(const float* __restrict__ logits,
               const float* __restrict__ temps,
               const float* __restrict__ noise,
               float* __restrict__ out)
{
    const int b    = blockIdx.x;
    const int tid  = threadIdx.x;
    const int lane = tid & 31;
    const int wid  = tid >> 5;            // 0..31

    const float t      = temps[b];
    const float safe_t = (t == 0.0f) ? 1.0f : t;
    const float inv_t  = 1.0f / safe_t;
    const float a      = inv_t * L2E;     // logit -> log2-domain scale

    const float* __restrict__ lrow = logits + (size_t)b * VV;
    const float* __restrict__ nrow = noise  + (size_t)b * VV;
    float4* __restrict__ prow      = (float4*)(out + BB + (size_t)b * VV);

    // pass 1: greedy argmax + Gumbel argmax + online exp-sum (base = running gv)
    float gv = -CUDART_INF_F; int gi = 0;
    float sv = -CUDART_INF_F; int si = 0;
    float s  = 0.0f;          // sum of exp2((l - gv)*a), rebased when gv moves

    // loop A: pinned region (uniform evict_last load path)
    int j = tid;
    for (; j < JPIN; j += NT) {
        float lv[8];
        ldg_el8(lrow + 8 * j, lv);
        P1_BODY(lv, j)
    }
    // loop B: unpinned tail (uniform plain load path; covered by LIFO pass 2)
    for (; j < NV8; j += NT) {
        float lv[8];
        ldg8(lrow + 8 * j, lv);
        P1_BODY(lv, j)
    }

    // ---- block reductions ----
    __shared__ float sh_gv[32]; __shared__ int sh_gi[32];
    __shared__ float sh_sv[32]; __shared__ int sh_si[32];
    __shared__ float sh_sum[32];
    __shared__ float fin_c;

    #pragma unroll
    for (int off = 16; off; off >>= 1) {
        float v  = __shfl_xor_sync(0xffffffffu, gv, off);
        int   i  = __shfl_xor_sync(0xffffffffu, gi, off);
        float ws = __shfl_xor_sync(0xffffffffu, s, off);
        if (v > gv) { s = fmaf(s, ex2a((gv - v) * a), ws); gv = v; gi = i; }
        else {
            s = fmaf(ws, ex2a((v - gv) * a), s);
            if (v == gv && i < gi) gi = i;
        }
        float v2 = __shfl_xor_sync(0xffffffffu, sv, off);
        int   i2 = __shfl_xor_sync(0xffffffffu, si, off);
        if (v2 > sv || (v2 == sv && i2 < si)) { sv = v2; si = i2; }
    }
    if (lane == 0) {
        sh_gv[wid] = gv; sh_gi[wid] = gi; sh_sum[wid] = s;
        sh_sv[wid] = sv; sh_si[wid] = si;
    }
    __syncthreads();

    if (wid == 0) {
        float v = sh_gv[lane]; int i = sh_gi[lane]; float c = sh_sum[lane];
        float v2 = sh_sv[lane]; int i2 = sh_si[lane];
        #pragma unroll
        for (int off = 16; off; off >>= 1) {
            float wv = __shfl_xor_sync(0xffffffffu, v, off);
            int   wi = __shfl_xor_sync(0xffffffffu, i, off);
            float wc = __shfl_xor_sync(0xffffffffu, c, off);
            if (wv > v) { c = fmaf(c, ex2a((v - wv) * a), wc); v = wv; i = wi; }
            else {
                c = fmaf(wc, ex2a((wv - v) * a), c);
                if (wv == v && wi < i) i = wi;
            }
            float wv2 = __shfl_xor_sync(0xffffffffu, v2, off);
            int   wi2 = __shfl_xor_sync(0xffffffffu, i2, off);
            if (wv2 > v2 || (wv2 == v2 && wi2 < i2)) { v2 = wv2; i2 = wi2; }
        }
        if (lane == 0) {
            // probs = exp2(l*a - max*a - log2(sum))
            fin_c = fmaf(-v, a, -log2f(c));
            out[b] = (float)((t == 0.0f) ? i : i2);
        }
    }
    __syncthreads();

    // ---- pass 2: probs = exp2(l*a + c) ----
    // REVERSE order (LIFO): the unpinned row tail is the freshest L2 content
    // after pass 1; the pinned head survives via evict_last. x2 unroll for MLP.
    const float c = fin_c;
    const float4* __restrict__ lrow4 = (const float4*)lrow;
    int j2 = NV4 - NT + tid;              // top chunk for this thread
    for (; j2 >= NT; j2 -= 2 * NT) {
        const float4 la = lrow4[j2];
        const float4 lb = lrow4[j2 - NT];
        float4 pa, pb;
        pa.x = ex2a(fmaf(la.x, a, c)); pa.y = ex2a(fmaf(la.y, a, c));
        pa.z = ex2a(fmaf(la.z, a, c)); pa.w = ex2a(fmaf(la.w, a, c));
        pb.x = ex2a(fmaf(lb.x, a, c)); pb.y = ex2a(fmaf(lb.y, a, c));
        pb.z = ex2a(fmaf(lb.z, a, c)); pb.w = ex2a(fmaf(lb.w, a, c));
        __stcs(prow + j2, pa);
        __stcs(prow + (j2 - NT), pb);
    }
    if (j2 >= 0) {
        const float4 la = lrow4[j2];
        float4 pa;
        pa.x = ex2a(fmaf(la.x, a, c)); pa.y = ex2a(fmaf(la.y, a, c));
        pa.z = ex2a(fmaf(la.z, a, c)); pa.w = ex2a(fmaf(la.w, a, c));
        __stcs(prow + j2, pa);
    }
}

extern "C" void kernel_launch(void* const* d_in, const int* in_sizes, int n_in,
                              void* d_out, int out_size) {
    const float* logits = (const float*)d_in[0];
    const float* temps  = (const float*)d_in[1];
    const float* noise  = (const float*)d_in[2];
    float* out = (float*)d_out;
    sampler_kernel<<<BB, NT>>>(logits, temps, noise, out);
}